// round 2
// baseline (speedup 1.0000x reference)
#include <cuda_runtime.h>
#include <cuda_bf16.h>
#include <math.h>

#define N_NODES 50000
#define E_EDGES 800000
#define HID 256
#define NCLASS 10
#define NGRAPH 512

// ---------------- device scratch (static allocation; no cudaMalloc allowed) ----
__device__ float g_h[(size_t)N_NODES * HID];     // 51.2 MB
__device__ float g_h2[(size_t)N_NODES * HID];    // 51.2 MB
__device__ float g_dinv[N_NODES];
__device__ int   g_deg[N_NODES];
__device__ int   g_indptr[N_NODES + 1];
__device__ int   g_cursor[N_NODES];
__device__ int   g_csrsrc[E_EDGES + N_NODES];
__device__ int   g_gstart[NGRAPH + 1];

// ---------------- graph preprocessing ----------------------------------------

__global__ void k_zero_deg() {
    int i = blockIdx.x * blockDim.x + threadIdx.x;
    if (i < N_NODES) g_deg[i] = 0;
}

__global__ void k_count_deg(const int* __restrict__ col) {
    int stride = gridDim.x * blockDim.x;
    for (int e = blockIdx.x * blockDim.x + threadIdx.x; e < E_EDGES; e += stride)
        atomicAdd(&g_deg[col[e]], 1);
}

__global__ void k_finalize_deg() {
    int i = blockIdx.x * blockDim.x + threadIdx.x;
    if (i < N_NODES) {
        int d = g_deg[i] + 1;          // + self loop
        g_deg[i] = d;
        g_dinv[i] = rsqrtf((float)d);  // d >= 1 always
    }
}

// single-block exclusive scan of g_deg -> g_indptr (50001 entries)
__global__ void k_scan_indptr() {
    __shared__ int s[1024];
    __shared__ int carry;
    int tid = threadIdx.x;
    if (tid == 0) carry = 0;
    __syncthreads();
    for (int base = 0; base < N_NODES; base += 1024) {
        int i = base + tid;
        int v = (i < N_NODES) ? g_deg[i] : 0;
        s[tid] = v;
        __syncthreads();
        for (int off = 1; off < 1024; off <<= 1) {
            int t = (tid >= off) ? s[tid - off] : 0;
            __syncthreads();
            s[tid] += t;
            __syncthreads();
        }
        int incl = s[tid];
        int total = s[1023];
        if (i < N_NODES) g_indptr[i] = carry + incl - v;
        __syncthreads();
        if (tid == 0) carry += total;
        __syncthreads();
    }
    if (tid == 0) g_indptr[N_NODES] = carry;
}

__global__ void k_copy_cursor() {
    int i = blockIdx.x * blockDim.x + threadIdx.x;
    if (i < N_NODES) g_cursor[i] = g_indptr[i];
}

__global__ void k_fill_csr(const int* __restrict__ row, const int* __restrict__ col) {
    int stride = gridDim.x * blockDim.x;
    for (int t = blockIdx.x * blockDim.x + threadIdx.x; t < E_EDGES + N_NODES; t += stride) {
        int v, srcv;
        if (t < E_EDGES) { v = col[t]; srcv = row[t]; }
        else             { v = t - E_EDGES; srcv = v; }  // self loop
        int p = atomicAdd(&g_cursor[v], 1);
        g_csrsrc[p] = srcv;
    }
}

// graph boundaries via binary search (batch is sorted)
__global__ void k_gstart(const int* __restrict__ batch) {
    int g = blockIdx.x * blockDim.x + threadIdx.x;
    if (g > NGRAPH) return;
    int lo = 0, hi = N_NODES;
    while (lo < hi) {
        int mid = (lo + hi) >> 1;
        if (batch[mid] < g) lo = mid + 1; else hi = mid;
    }
    g_gstart[g] = lo;
}

// ---------------- GEMM: C[M,256] = A[M,256] * B[256,256] (+ bias) -------------
// BM=128, BN=64, BK=16, 256 threads, each thread computes 8x4.

__global__ __launch_bounds__(256) void k_gemm(const float* __restrict__ A,
                                              const float* __restrict__ B,
                                              const float* __restrict__ bias,
                                              float* __restrict__ C, int M) {
    const int BM = 128, BN = 64, BK = 16, K = 256, NN = 256;
    __shared__ float Ast[BK][BM + 4];   // k-major, pad 4 keeps float4 alignment
    __shared__ float Bs[BK][BN];

    int tid = threadIdx.x;
    int bm = blockIdx.x * BM;
    int bn = blockIdx.y * BN;
    int tx = tid & 15;       // 0..15 -> 4 output cols each
    int ty = tid >> 4;       // 0..15 -> 8 output rows each

    float acc[8][4];
#pragma unroll
    for (int i = 0; i < 8; i++)
#pragma unroll
        for (int j = 0; j < 4; j++) acc[i][j] = 0.0f;

    int arow0 = tid >> 2;          // 0..63
    int acol4 = (tid & 3) * 4;     // k offset within tile
    int bk = tid >> 4;             // 0..15
    int bn4 = (tid & 15) * 4;

    for (int k0 = 0; k0 < K; k0 += BK) {
        // load A tile (128x16) as k-major
#pragma unroll
        for (int h = 0; h < 2; h++) {
            int r = arow0 + h * 64;
            float4 v = make_float4(0.f, 0.f, 0.f, 0.f);
            if (bm + r < M)
                v = *(const float4*)&A[(size_t)(bm + r) * K + k0 + acol4];
            Ast[acol4 + 0][r] = v.x;
            Ast[acol4 + 1][r] = v.y;
            Ast[acol4 + 2][r] = v.z;
            Ast[acol4 + 3][r] = v.w;
        }
        // load B tile (16x64)
        {
            float4 v = *(const float4*)&B[(size_t)(k0 + bk) * NN + bn + bn4];
            *(float4*)&Bs[bk][bn4] = v;
        }
        __syncthreads();
#pragma unroll
        for (int k = 0; k < BK; k++) {
            float4 a0 = *(const float4*)&Ast[k][ty * 8];
            float4 a1 = *(const float4*)&Ast[k][ty * 8 + 4];
            float4 b4 = *(const float4*)&Bs[k][tx * 4];
            float a[8] = {a0.x, a0.y, a0.z, a0.w, a1.x, a1.y, a1.z, a1.w};
            float bb[4] = {b4.x, b4.y, b4.z, b4.w};
#pragma unroll
            for (int i = 0; i < 8; i++)
#pragma unroll
                for (int j = 0; j < 4; j++) acc[i][j] += a[i] * bb[j];
        }
        __syncthreads();
    }

    float4 badd = make_float4(0.f, 0.f, 0.f, 0.f);
    if (bias) badd = *(const float4*)&bias[bn + tx * 4];
#pragma unroll
    for (int i = 0; i < 8; i++) {
        int r = bm + ty * 8 + i;
        if (r < M) {
            float4 o = make_float4(acc[i][0] + badd.x, acc[i][1] + badd.y,
                                   acc[i][2] + badd.z, acc[i][3] + badd.w);
            *(float4*)&C[(size_t)r * NN + bn + tx * 4] = o;
        }
    }
}

// ---------------- pull-based GCN aggregation ----------------------------------
// out[v,f] = relu( dinv[v] * sum_{src in CSR[v]} h2[src,f]*dinv[src]  + b[f] )
// 64 threads per node (float4 per thread), 4 nodes per 256-thread block.

__global__ __launch_bounds__(256) void k_aggregate(const float* __restrict__ h2,
                                                   const float* __restrict__ b,
                                                   float* __restrict__ out) {
    int node = blockIdx.x * 4 + (threadIdx.x >> 6);
    int f4 = (threadIdx.x & 63) * 4;
    if (node >= N_NODES) return;

    int s = g_indptr[node];
    int e = g_indptr[node + 1];
    float dv = g_dinv[node];

    float4 acc = make_float4(0.f, 0.f, 0.f, 0.f);
    for (int i = s; i < e; i++) {
        int src = g_csrsrc[i];
        float w = g_dinv[src];
        float4 v = *(const float4*)&h2[(size_t)src * HID + f4];
        acc.x += v.x * w;
        acc.y += v.y * w;
        acc.z += v.z * w;
        acc.w += v.w * w;
    }
    float4 bb = *(const float4*)&b[f4];
    float4 o;
    o.x = fmaxf(acc.x * dv + bb.x, 0.f);
    o.y = fmaxf(acc.y * dv + bb.y, 0.f);
    o.z = fmaxf(acc.z * dv + bb.z, 0.f);
    o.w = fmaxf(acc.w * dv + bb.w, 0.f);
    *(float4*)&out[(size_t)node * HID + f4] = o;
}

// ---------------- fused mean-pool + classifier --------------------------------
// one block per graph; batch is sorted so nodes are contiguous.

__global__ __launch_bounds__(256) void k_pool_cls(const float* __restrict__ h,
                                                  const float* __restrict__ outW,
                                                  const float* __restrict__ outb,
                                                  float* __restrict__ out) {
    int g = blockIdx.x;
    int tid = threadIdx.x;  // one feature per thread
    __shared__ float sp[HID];

    int s = g_gstart[g];
    int e = g_gstart[g + 1];
    float acc = 0.f;
    for (int n = s; n < e; n++) acc += h[(size_t)n * HID + tid];
    float cnt = (float)(e - s);
    sp[tid] = acc / fmaxf(cnt, 1.0f);
    __syncthreads();

    if (tid < NCLASS) {
        float o = outb[tid];
#pragma unroll 8
        for (int f = 0; f < HID; f++) o += sp[f] * outW[f * NCLASS + tid];
        out[g * NCLASS + tid] = o;
    }
}

// ---------------- launch ------------------------------------------------------

extern "C" void kernel_launch(void* const* d_in, const int* in_sizes, int n_in,
                              void* d_out, int out_size) {
    const float* x      = (const float*)d_in[0];
    const int*   eidx   = (const int*)d_in[1];
    const int*   batch  = (const int*)d_in[2];
    const float* enc_W  = (const float*)d_in[3];
    const float* enc_b  = (const float*)d_in[4];
    const float* conv_W = (const float*)d_in[5];
    const float* conv_b = (const float*)d_in[6];
    const float* out_W  = (const float*)d_in[7];
    const float* out_b  = (const float*)d_in[8];
    float* out = (float*)d_out;

    const int* row = eidx;            // edge_index[0]
    const int* col = eidx + E_EDGES;  // edge_index[1]

    // --- graph structure (rebuilt every call; deterministic up to fp assoc) ---
    k_zero_deg<<<(N_NODES + 255) / 256, 256>>>();
    k_count_deg<<<2048, 256>>>(col);
    k_finalize_deg<<<(N_NODES + 255) / 256, 256>>>();
    k_scan_indptr<<<1, 1024>>>();
    k_copy_cursor<<<(N_NODES + 255) / 256, 256>>>();
    k_fill_csr<<<2048, 256>>>(row, col);
    k_gstart<<<2, 512>>>(batch);

    float* g_h_ptr;  cudaGetSymbolAddress((void**)&g_h_ptr,  g_h);
    float* g_h2_ptr; cudaGetSymbolAddress((void**)&g_h2_ptr, g_h2);

    dim3 ggrid((N_NODES + 127) / 128, 256 / 64);

    // encoder: h = x @ enc_W + enc_b
    k_gemm<<<ggrid, 256>>>(x, enc_W, enc_b, g_h_ptr, N_NODES);

    // layer 0
    k_gemm<<<ggrid, 256>>>(g_h_ptr, conv_W, nullptr, g_h2_ptr, N_NODES);
    k_aggregate<<<(N_NODES + 3) / 4, 256>>>(g_h2_ptr, conv_b, g_h_ptr);

    // layer 1
    k_gemm<<<ggrid, 256>>>(g_h_ptr, conv_W + HID * HID, nullptr, g_h2_ptr, N_NODES);
    k_aggregate<<<(N_NODES + 3) / 4, 256>>>(g_h2_ptr, conv_b + HID, g_h_ptr);

    // pool + classify
    k_pool_cls<<<NGRAPH, 256>>>(g_h_ptr, out_W, out_b, out);
}

// round 4
// speedup vs baseline: 2.1404x; 2.1404x over previous
#include <cuda_runtime.h>
#include <cuda_bf16.h>
#include <math.h>
#include <stdint.h>

#define N_NODES 50000
#define E_EDGES 800000
#define HID 256
#define NCLASS 10
#define NGRAPH 512

// ---------------- device scratch (static; no cudaMalloc allowed) --------------
__device__ float g_h[(size_t)N_NODES * HID];     // 51.2 MB
__device__ float g_h2[(size_t)N_NODES * HID];    // 51.2 MB
__device__ float g_Wt[3 * HID * HID];            // tf32-rounded weights [K][N]
__device__ float g_dinv[N_NODES];
__device__ int   g_deg[N_NODES];
__device__ int   g_indptr[N_NODES + 1];
__device__ int   g_cursor[N_NODES];
__device__ int   g_csrsrc[E_EDGES + N_NODES];
__device__ int   g_gstart[NGRAPH + 1];
__device__ int   g_part[64];

// ---------------- helpers -----------------------------------------------------
__device__ __forceinline__ uint32_t smem_u32(const void* p) {
    uint32_t a;
    asm("{ .reg .u64 t; cvta.to.shared.u64 t, %1; cvt.u32.u64 %0, t; }" : "=r"(a) : "l"(p));
    return a;
}
__device__ __forceinline__ uint32_t f2tf32(float f) {
    uint32_t o;
    asm("cvt.rna.tf32.f32 %0, %1;" : "=r"(o) : "f"(f));
    return o;
}
__device__ __forceinline__ void mma_tf32(float* d, const uint32_t* a, const uint32_t* b) {
    asm volatile(
        "mma.sync.aligned.m16n8k8.row.col.f32.tf32.tf32.f32 "
        "{%0,%1,%2,%3}, {%4,%5,%6,%7}, {%8,%9}, {%0,%1,%2,%3};"
        : "+f"(d[0]), "+f"(d[1]), "+f"(d[2]), "+f"(d[3])
        : "r"(a[0]), "r"(a[1]), "r"(a[2]), "r"(a[3]), "r"(b[0]), "r"(b[1]));
}
#define CP_ASYNC16(dst, src, sz) \
    asm volatile("cp.async.cg.shared.global [%0], [%1], 16, %2;" :: "r"(dst), "l"(src), "r"(sz))
#define CP_COMMIT()   asm volatile("cp.async.commit_group;" ::: "memory")
#define CP_WAIT(n)    asm volatile("cp.async.wait_group %0;" :: "n"(n) : "memory")

// ---------------- graph preprocessing ----------------------------------------
__global__ void k_zero_deg() {
    int i = blockIdx.x * blockDim.x + threadIdx.x;
    if (i < N_NODES) g_deg[i] = 0;
}
__global__ void k_count_deg(const int* __restrict__ col) {
    int stride = gridDim.x * blockDim.x;
    for (int e = blockIdx.x * blockDim.x + threadIdx.x; e < E_EDGES; e += stride)
        atomicAdd(&g_deg[col[e]], 1);
}
__global__ void k_finalize_deg() {
    int i = blockIdx.x * blockDim.x + threadIdx.x;
    if (i < N_NODES) {
        int d = g_deg[i] + 1;
        g_deg[i] = d;
        g_dinv[i] = rsqrtf((float)d);
    }
}
__global__ void k_scan_local() {
    __shared__ int s[1024];
    int tid = threadIdx.x;
    int i = blockIdx.x * 1024 + tid;
    int v = (i < N_NODES) ? g_deg[i] : 0;
    s[tid] = v;
    __syncthreads();
    for (int off = 1; off < 1024; off <<= 1) {
        int t = (tid >= off) ? s[tid - off] : 0;
        __syncthreads();
        s[tid] += t;
        __syncthreads();
    }
    if (i < N_NODES) g_indptr[i] = s[tid] - v;
    if (tid == 1023) g_part[blockIdx.x] = s[1023];
}
__global__ void k_scan_part() {
    __shared__ int s[64];
    int t = threadIdx.x;
    int nb = (N_NODES + 1023) / 1024;
    int v = (t < nb) ? g_part[t] : 0;
    s[t] = v;
    __syncthreads();
    for (int off = 1; off < 64; off <<= 1) {
        int x = (t >= off) ? s[t - off] : 0;
        __syncthreads();
        s[t] += x;
        __syncthreads();
    }
    g_part[t] = s[t] - v;
}
__global__ void k_scan_add() {
    int i = blockIdx.x * 1024 + threadIdx.x;
    if (i < N_NODES) {
        int v = g_indptr[i] + g_part[blockIdx.x];
        g_indptr[i] = v;
        g_cursor[i] = v;
    }
    if (i == 0) g_indptr[N_NODES] = E_EDGES + N_NODES;
}
__global__ void k_fill_csr(const int* __restrict__ row, const int* __restrict__ col) {
    int stride = gridDim.x * blockDim.x;
    for (int t = blockIdx.x * blockDim.x + threadIdx.x; t < E_EDGES + N_NODES; t += stride) {
        int v, srcv;
        if (t < E_EDGES) { v = col[t]; srcv = row[t]; }
        else             { v = t - E_EDGES; srcv = v; }
        int p = atomicAdd(&g_cursor[v], 1);
        g_csrsrc[p] = srcv;
    }
}
__global__ void k_gstart(const int* __restrict__ batch) {
    int g = blockIdx.x * blockDim.x + threadIdx.x;
    if (g > NGRAPH) return;
    int lo = 0, hi = N_NODES;
    while (lo < hi) {
        int mid = (lo + hi) >> 1;
        if (batch[mid] < g) lo = mid + 1; else hi = mid;
    }
    g_gstart[g] = lo;
}

// ---------------- weight tf32 pre-rounding (no transpose: [K][N] kept) --------
__global__ void k_prep_w(const float* __restrict__ enc_W, const float* __restrict__ conv_W) {
    int id = blockIdx.x * blockDim.x + threadIdx.x;
    if (id >= 3 * HID * HID) return;
    int w = id / (HID * HID);
    int off = id - w * HID * HID;
    float v = (w == 0) ? enc_W[off] : conv_W[(w - 1) * HID * HID + off];
    ((uint32_t*)g_Wt)[id] = f2tf32(v);
}

// ---------------- tf32 mma.sync GEMM: C[M,256] = A[M,256] @ W[256,256] --------
// Block 128x128, 8 warps (4x2), warp tile 32x64. K chunks of 32, cp.async DB.
#define A_PITCH 36    // words per A smem row (128 rows)
#define B_PITCH 136   // words per B smem row (32 rows)
#define A_TILE_B (128 * A_PITCH * 4)   // 18432
#define B_TILE_B (32 * B_PITCH * 4)    // 17408
#define BUF_B    (A_TILE_B + B_TILE_B) // 35840
#define GEMM_SMEM (2 * BUF_B)          // 71680

__global__ void __launch_bounds__(256, 2)
k_gemm_tc(const float* __restrict__ A, const float* __restrict__ W,
          const float* __restrict__ bias, float* __restrict__ C, int M) {
    extern __shared__ char smem[];
    uint32_t sb = smem_u32(smem);
    int tid = threadIdx.x;
    int lane = tid & 31, wid = tid >> 5;
    int warp_m = wid & 3, warp_n = wid >> 2;
    int g = lane >> 2, tig = lane & 3;
    int bm = blockIdx.x * 128;
    int bn = blockIdx.y * 128;

    float acc[2][8][4];
#pragma unroll
    for (int mt = 0; mt < 2; mt++)
#pragma unroll
        for (int nt = 0; nt < 8; nt++)
#pragma unroll
            for (int j = 0; j < 4; j++) acc[mt][nt][j] = 0.f;

    // cp.async chunk loader: A 128x32, B 32x128 (cols bn..bn+127)
    auto load_chunk = [&](int c, int buf) {
        int k0 = c * 32;
        uint32_t abase = sb + buf * BUF_B;
        uint32_t bbase = abase + A_TILE_B;
#pragma unroll
        for (int i = 0; i < 4; i++) {
            int f = tid + i * 256;          // 0..1023
            int row = f >> 3, c4 = f & 7;   // A: 8 float4 per row
            int gr = bm + row;
            const float* src = A + (size_t)gr * HID + k0 + c4 * 4;
            uint32_t dst = abase + (row * A_PITCH + c4 * 4) * 4;
            uint32_t sz = (gr < M) ? 16u : 0u;
            CP_ASYNC16(dst, src, sz);
        }
#pragma unroll
        for (int i = 0; i < 4; i++) {
            int f = tid + i * 256;
            int row = f >> 5, c4 = f & 31;  // B: 32 float4 per row
            const float* src = W + (size_t)(k0 + row) * HID + bn + c4 * 4;
            uint32_t dst = bbase + (row * B_PITCH + c4 * 4) * 4;
            CP_ASYNC16(dst, src, 16u);
        }
        CP_COMMIT();
    };

    load_chunk(0, 0);

    for (int c = 0; c < 8; c++) {
        int buf = c & 1;
        if (c < 7) {
            load_chunk(c + 1, buf ^ 1);
            CP_WAIT(1);
        } else {
            CP_WAIT(0);
        }
        __syncthreads();

        const uint32_t* As = (const uint32_t*)(smem + buf * BUF_B);
        const uint32_t* Bs = (const uint32_t*)(smem + buf * BUF_B + A_TILE_B);

#pragma unroll
        for (int ks = 0; ks < 4; ks++) {
            int kl = ks * 8;
            uint32_t afr[2][4];
#pragma unroll
            for (int mt = 0; mt < 2; mt++) {
                int m0 = warp_m * 32 + mt * 16;
                afr[mt][0] = As[(m0 + g) * A_PITCH + kl + tig];
                afr[mt][1] = As[(m0 + 8 + g) * A_PITCH + kl + tig];
                afr[mt][2] = As[(m0 + g) * A_PITCH + kl + tig + 4];
                afr[mt][3] = As[(m0 + 8 + g) * A_PITCH + kl + tig + 4];
            }
            uint32_t bfr[8][2];
#pragma unroll
            for (int nt = 0; nt < 8; nt++) {
                int n0 = warp_n * 64 + nt * 8;
                bfr[nt][0] = Bs[(kl + tig) * B_PITCH + n0 + g];
                bfr[nt][1] = Bs[(kl + tig + 4) * B_PITCH + n0 + g];
            }
#pragma unroll
            for (int mt = 0; mt < 2; mt++)
#pragma unroll
                for (int nt = 0; nt < 8; nt++)
                    mma_tf32(acc[mt][nt], afr[mt], bfr[nt]);
        }
        __syncthreads();
    }

    // epilogue
#pragma unroll
    for (int mt = 0; mt < 2; mt++) {
        int m_base = bm + warp_m * 32 + mt * 16;
        int row0 = m_base + g;
        int row1 = m_base + 8 + g;
#pragma unroll
        for (int nt = 0; nt < 8; nt++) {
            int n = bn + warp_n * 64 + nt * 8 + 2 * tig;
            float2 badd = make_float2(0.f, 0.f);
            if (bias) badd = *(const float2*)&bias[n];
            if (row0 < M) {
                float2 o = make_float2(acc[mt][nt][0] + badd.x, acc[mt][nt][1] + badd.y);
                *(float2*)&C[(size_t)row0 * HID + n] = o;
            }
            if (row1 < M) {
                float2 o = make_float2(acc[mt][nt][2] + badd.x, acc[mt][nt][3] + badd.y);
                *(float2*)&C[(size_t)row1 * HID + n] = o;
            }
        }
    }
}

// ---------------- pull-based GCN aggregation ----------------------------------
__global__ __launch_bounds__(256) void k_aggregate(const float* __restrict__ h2,
                                                   const float* __restrict__ b,
                                                   float* __restrict__ out) {
    int node = blockIdx.x * 4 + (threadIdx.x >> 6);
    int f4 = (threadIdx.x & 63) * 4;
    if (node >= N_NODES) return;

    int s = g_indptr[node];
    int e = g_indptr[node + 1];
    float dv = g_dinv[node];

    float4 acc = make_float4(0.f, 0.f, 0.f, 0.f);
    for (int i = s; i < e; i++) {
        int src = g_csrsrc[i];
        float w = g_dinv[src];
        float4 v = *(const float4*)&h2[(size_t)src * HID + f4];
        acc.x += v.x * w;
        acc.y += v.y * w;
        acc.z += v.z * w;
        acc.w += v.w * w;
    }
    float4 bb = *(const float4*)&b[f4];
    float4 o;
    o.x = fmaxf(acc.x * dv + bb.x, 0.f);
    o.y = fmaxf(acc.y * dv + bb.y, 0.f);
    o.z = fmaxf(acc.z * dv + bb.z, 0.f);
    o.w = fmaxf(acc.w * dv + bb.w, 0.f);
    *(float4*)&out[(size_t)node * HID + f4] = o;
}

// ---------------- fused mean-pool + classifier --------------------------------
__global__ __launch_bounds__(256) void k_pool_cls(const float* __restrict__ h,
                                                  const float* __restrict__ outW,
                                                  const float* __restrict__ outb,
                                                  float* __restrict__ out) {
    int g = blockIdx.x;
    int tid = threadIdx.x;
    __shared__ float sp[HID];

    int s = g_gstart[g];
    int e = g_gstart[g + 1];
    float acc = 0.f;
    for (int n = s; n < e; n++) acc += h[(size_t)n * HID + tid];
    float cnt = (float)(e - s);
    sp[tid] = acc / fmaxf(cnt, 1.0f);
    __syncthreads();

    if (tid < NCLASS) {
        float o = outb[tid];
#pragma unroll 8
        for (int f = 0; f < HID; f++) o += sp[f] * outW[f * NCLASS + tid];
        out[g * NCLASS + tid] = o;
    }
}

// ---------------- launch ------------------------------------------------------
extern "C" void kernel_launch(void* const* d_in, const int* in_sizes, int n_in,
                              void* d_out, int out_size) {
    const float* x      = (const float*)d_in[0];
    const int*   eidx   = (const int*)d_in[1];
    const int*   batch  = (const int*)d_in[2];
    const float* enc_W  = (const float*)d_in[3];
    const float* enc_b  = (const float*)d_in[4];
    const float* conv_W = (const float*)d_in[5];
    const float* conv_b = (const float*)d_in[6];
    const float* out_W  = (const float*)d_in[7];
    const float* out_b  = (const float*)d_in[8];
    float* out = (float*)d_out;

    const int* row = eidx;
    const int* col = eidx + E_EDGES;

    static bool attr_done = false;
    if (!attr_done) {
        cudaFuncSetAttribute(k_gemm_tc, cudaFuncAttributeMaxDynamicSharedMemorySize, GEMM_SMEM);
        attr_done = true;
    }

    int nb = (N_NODES + 1023) / 1024;   // 49

    k_zero_deg<<<(N_NODES + 255) / 256, 256>>>();
    k_count_deg<<<2048, 256>>>(col);
    k_finalize_deg<<<(N_NODES + 255) / 256, 256>>>();
    k_scan_local<<<nb, 1024>>>();
    k_scan_part<<<1, 64>>>();
    k_scan_add<<<nb, 1024>>>();
    k_fill_csr<<<2048, 256>>>(row, col);
    k_gstart<<<2, 512>>>(batch);
    k_prep_w<<<(3 * HID * HID + 255) / 256, 256>>>(enc_W, conv_W);

    float* g_h_ptr;  cudaGetSymbolAddress((void**)&g_h_ptr,  g_h);
    float* g_h2_ptr; cudaGetSymbolAddress((void**)&g_h2_ptr, g_h2);
    float* g_Wt_ptr; cudaGetSymbolAddress((void**)&g_Wt_ptr, g_Wt);

    dim3 ggrid((N_NODES + 127) / 128, 2);   // 391 x 2

    // encoder
    k_gemm_tc<<<ggrid, 256, GEMM_SMEM>>>(x, g_Wt_ptr, enc_b, g_h_ptr, N_NODES);
    // layer 0
    k_gemm_tc<<<ggrid, 256, GEMM_SMEM>>>(g_h_ptr, g_Wt_ptr + HID * HID, nullptr, g_h2_ptr, N_NODES);
    k_aggregate<<<(N_NODES + 3) / 4, 256>>>(g_h2_ptr, conv_b, g_h_ptr);
    // layer 1
    k_gemm_tc<<<ggrid, 256, GEMM_SMEM>>>(g_h_ptr, g_Wt_ptr + 2 * HID * HID, nullptr, g_h2_ptr, N_NODES);
    k_aggregate<<<(N_NODES + 3) / 4, 256>>>(g_h2_ptr, conv_b + HID, g_h_ptr);
    // pool + classify
    k_pool_cls<<<NGRAPH, 256>>>(g_h_ptr, out_W, out_b, out);
}